// round 11
// baseline (speedup 1.0000x reference)
#include <cuda_runtime.h>
#include <cstdint>

#define MAXN 50000
#define MAXE 600000

// ---------------- scratch ----------------
__device__ __align__(16) float g_deg[MAXN];        // dinv = rsqrt(1 + indeg)
__device__ int   g_cnt[MAXN];
__device__ int   g_off[MAXN + 1];
__device__ int   g_pos[MAXN];
__device__ int   g_csr[MAXE];
__device__ int   g_bsum[256];
__device__ __align__(16) float g_agg[MAXN * 128];
__device__ __align__(16) float g_h1 [MAXN * 256];
__device__ __align__(16) float g_t  [MAXN * 128];
__device__ __align__(16) float g_t3 [MAXN * 2];
__device__ int g_is32 = 0;   // probe only ever sets 1 (idempotent across graph replays)

// ---------------- graph prep ----------------
__global__ void k_init(const unsigned* __restrict__ w, int n) {
    int i = blockIdx.x * blockDim.x + threadIdx.x;
    if (i < n) g_cnt[i] = 0;
    if (i < 2048 && w[2 * i + 1] != 0u) g_is32 = 1;
}

__device__ __forceinline__ void decode_edge(const void* ei, int e, int E, int N, int& s, int& d) {
    if (g_is32) {
        const int* p = (const int*)ei;
        s = p[e]; d = p[E + e];
    } else {
        const long long* p = (const long long*)ei;
        s = (int)p[e]; d = (int)p[E + e];
    }
    s = min(max(s, 0), N - 1);
    d = min(max(d, 0), N - 1);
}

__global__ void k_count(const void* __restrict__ ei, int E, int N) {
    int e = blockIdx.x * blockDim.x + threadIdx.x;
    if (e >= E) return;
    int s, d;
    decode_edge(ei, e, E, N, s, d);
    atomicAdd(&g_cnt[d], 1);
}

__global__ __launch_bounds__(256) void k_scan1(int N) {
    __shared__ int sh[256];
    int i = blockIdx.x * 256 + threadIdx.x;
    int t = threadIdx.x;
    int v = (i < N) ? g_cnt[i] : 0;
    sh[t] = v;
    __syncthreads();
#pragma unroll
    for (int off = 1; off < 256; off <<= 1) {
        int u = (t >= off) ? sh[t - off] : 0;
        __syncthreads();
        sh[t] += u;
        __syncthreads();
    }
    if (i < N) g_off[i] = sh[t] - v;
    if (t == 255) g_bsum[blockIdx.x] = sh[255];
}

__global__ __launch_bounds__(256) void k_scan23(int nBlocks, int N) {
    __shared__ int sh[256];
    int t = threadIdx.x;
    int v = (t < nBlocks) ? g_bsum[t] : 0;
    sh[t] = v;
    __syncthreads();
#pragma unroll
    for (int off = 1; off < 256; off <<= 1) {
        int u = (t >= off) ? sh[t - off] : 0;
        __syncthreads();
        sh[t] += u;
        __syncthreads();
    }
    int pre = (blockIdx.x > 0) ? sh[blockIdx.x - 1] : 0;
    int i = blockIdx.x * 256 + t;
    if (i < N) {
        int o = g_off[i] + pre;
        g_off[i] = o;
        g_pos[i] = o;
        g_deg[i] = rsqrtf((float)(1 + g_cnt[i]));
    }
    if (blockIdx.x == 0 && t == 0) g_off[N] = sh[nBlocks - 1];
}

__global__ void k_fill(const void* __restrict__ ei, int E, int N) {
    int e = blockIdx.x * blockDim.x + threadIdx.x;
    if (e >= E) return;
    int s, d;
    decode_edge(ei, e, E, N, s, d);
    int p = atomicAdd(&g_pos[d], 1);
    g_csr[p] = s;
}

// ---------------- pull aggregation (C = 128) ----------------
__global__ __launch_bounds__(256) void k_pull128(const float* __restrict__ h,
                                                 float* __restrict__ out, int N) {
    int d = blockIdx.x * (blockDim.x >> 5) + (threadIdx.x >> 5);
    if (d >= N) return;
    int lane = threadIdx.x & 31;
    float dd = g_deg[d];
    float4 acc = ((const float4*)(h + (size_t)d * 128))[lane];
    float nms = dd * dd;
    acc.x *= nms; acc.y *= nms; acc.z *= nms; acc.w *= nms;
    const int beg = g_off[d], end = g_off[d + 1];
    for (int base = beg; base < end; base += 32) {
        int cnt = min(end - base, 32);
        int e = base + lane;
        int sE = (lane < cnt) ? g_csr[e] : 0;
        float nmE = (lane < cnt) ? g_deg[sE] * dd : 0.f;
        int j = 0;
        for (; j + 2 <= cnt; j += 2) {
            int   s0 = __shfl_sync(0xffffffffu, sE,  j);
            int   s1 = __shfl_sync(0xffffffffu, sE,  j + 1);
            float n0 = __shfl_sync(0xffffffffu, nmE, j);
            float n1 = __shfl_sync(0xffffffffu, nmE, j + 1);
            float4 v0 = ((const float4*)(h + (size_t)s0 * 128))[lane];
            float4 v1 = ((const float4*)(h + (size_t)s1 * 128))[lane];
            acc.x += n0 * v0.x + n1 * v1.x;
            acc.y += n0 * v0.y + n1 * v1.y;
            acc.z += n0 * v0.z + n1 * v1.z;
            acc.w += n0 * v0.w + n1 * v1.w;
        }
        if (j < cnt) {
            int   s0 = __shfl_sync(0xffffffffu, sE,  j);
            float n0 = __shfl_sync(0xffffffffu, nmE, j);
            float4 v0 = ((const float4*)(h + (size_t)s0 * 128))[lane];
            acc.x += n0 * v0.x; acc.y += n0 * v0.y;
            acc.z += n0 * v0.z; acc.w += n0 * v0.w;
        }
    }
    ((float4*)(out + (size_t)d * 128))[lane] = acc;
}

// ---------------- SGEMM, packed fma.rn.f32x2, BK=8, register prefetch ----------------
// MODE 0: C = relu(out + bias), MODE 1: C = out
template<int MODE>
__global__ __launch_bounds__(256) void k_sgemm_pf(
    int M, int Ntot, int K,
    const float* __restrict__ A, const float* __restrict__ B,
    const float* __restrict__ bias, float* __restrict__ C)
{
    __shared__ float As[8][128];
    __shared__ float Bs[8][128];
    const int tid = threadIdx.x;
    const int br = blockIdx.y, bc = blockIdx.x;
    const int rowA = tid >> 1;
    const int colA = (tid & 1) << 2;
    const int rowB = tid >> 5;
    const int colB = (tid & 31) << 2;
    const int tr = (tid >> 4) << 3;
    const int tc = (tid & 15) << 3;

    unsigned long long acc[8][4];
#pragma unroll
    for (int i = 0; i < 8; i++)
#pragma unroll
        for (int j = 0; j < 4; j++) acc[i][j] = 0ull;

    const int aRow = br * 128 + rowA;
    const bool aValid = aRow < M;
    const float* Ag = A + (size_t)aRow * K + colA;
    const float* Bg = B + (size_t)rowB * Ntot + bc * 128 + colB;

    float4 av = aValid ? *(const float4*)(Ag) : make_float4(0.f, 0.f, 0.f, 0.f);
    float4 bv = *(const float4*)(Bg);
    As[colA + 0][rowA] = av.x;
    As[colA + 1][rowA] = av.y;
    As[colA + 2][rowA] = av.z;
    As[colA + 3][rowA] = av.w;
    *(float4*)&Bs[rowB][colB] = bv;
    __syncthreads();

    for (int k0 = 0; k0 < K; k0 += 8) {
        const bool more = (k0 + 8) < K;
        if (more) {
            av = aValid ? *(const float4*)(Ag + k0 + 8) : make_float4(0.f, 0.f, 0.f, 0.f);
            bv = *(const float4*)(Bg + (size_t)(k0 + 8) * Ntot);
        }
#pragma unroll
        for (int k = 0; k < 8; ++k) {
            float4 ra0 = *(const float4*)&As[k][tr];
            float4 ra1 = *(const float4*)&As[k][tr + 4];
            unsigned long long b2[4];
#pragma unroll
            for (int j = 0; j < 4; j++)
                b2[j] = *(const unsigned long long*)&Bs[k][tc + j * 2];
            float ras[8] = {ra0.x, ra0.y, ra0.z, ra0.w, ra1.x, ra1.y, ra1.z, ra1.w};
#pragma unroll
            for (int i = 0; i < 8; i++) {
                unsigned long long a2;
                asm("mov.b64 %0, {%1, %1};" : "=l"(a2) : "f"(ras[i]));
#pragma unroll
                for (int j = 0; j < 4; j++)
                    asm("fma.rn.f32x2 %0, %1, %2, %3;"
                        : "=l"(acc[i][j]) : "l"(a2), "l"(b2[j]), "l"(acc[i][j]));
            }
        }
        __syncthreads();
        if (more) {
            As[colA + 0][rowA] = av.x;
            As[colA + 1][rowA] = av.y;
            As[colA + 2][rowA] = av.z;
            As[colA + 3][rowA] = av.w;
            *(float4*)&Bs[rowB][colB] = bv;
            __syncthreads();
        }
    }

#pragma unroll
    for (int i = 0; i < 8; i++) {
        int r = br * 128 + tr + i;
        if (r >= M) break;
#pragma unroll
        for (int jj = 0; jj < 2; jj++) {
            int c = bc * 128 + tc + jj * 4;
            float4 v;
            asm("mov.b64 {%0, %1}, %2;" : "=f"(v.x), "=f"(v.y) : "l"(acc[i][jj * 2 + 0]));
            asm("mov.b64 {%0, %1}, %2;" : "=f"(v.z), "=f"(v.w) : "l"(acc[i][jj * 2 + 1]));
            if (MODE == 0) {
                const float4 bb = *(const float4*)(bias + c);
                v.x = fmaxf(v.x + bb.x, 0.f);
                v.y = fmaxf(v.y + bb.y, 0.f);
                v.z = fmaxf(v.z + bb.z, 0.f);
                v.w = fmaxf(v.w + bb.w, 0.f);
            }
            *(float4*)&C[(size_t)r * Ntot + c] = v;
        }
    }
}

// ---------------- fused pull(t) + bias2 + relu + W3 projection -> t3 ----------------
// Per dst-node warp: acc = A-aggregate of t; h2 = relu(acc + b2); t3 = h2 @ W3
__global__ __launch_bounds__(256) void k_pull_gemm3(const float* __restrict__ t,
                                                    const float* __restrict__ b2,
                                                    const float* __restrict__ W3, int N) {
    int d = blockIdx.x * (blockDim.x >> 5) + (threadIdx.x >> 5);
    if (d >= N) return;
    int lane = threadIdx.x & 31;
    float dd = g_deg[d];
    float4 acc = ((const float4*)(t + (size_t)d * 128))[lane];
    float nms = dd * dd;
    acc.x *= nms; acc.y *= nms; acc.z *= nms; acc.w *= nms;
    const int beg = g_off[d], end = g_off[d + 1];
    for (int base = beg; base < end; base += 32) {
        int cnt = min(end - base, 32);
        int e = base + lane;
        int sE = (lane < cnt) ? g_csr[e] : 0;
        float nmE = (lane < cnt) ? g_deg[sE] * dd : 0.f;
        int j = 0;
        for (; j + 2 <= cnt; j += 2) {
            int   s0 = __shfl_sync(0xffffffffu, sE,  j);
            int   s1 = __shfl_sync(0xffffffffu, sE,  j + 1);
            float n0 = __shfl_sync(0xffffffffu, nmE, j);
            float n1 = __shfl_sync(0xffffffffu, nmE, j + 1);
            float4 v0 = ((const float4*)(t + (size_t)s0 * 128))[lane];
            float4 v1 = ((const float4*)(t + (size_t)s1 * 128))[lane];
            acc.x += n0 * v0.x + n1 * v1.x;
            acc.y += n0 * v0.y + n1 * v1.y;
            acc.z += n0 * v0.z + n1 * v1.z;
            acc.w += n0 * v0.w + n1 * v1.w;
        }
        if (j < cnt) {
            int   s0 = __shfl_sync(0xffffffffu, sE,  j);
            float n0 = __shfl_sync(0xffffffffu, nmE, j);
            float4 v0 = ((const float4*)(t + (size_t)s0 * 128))[lane];
            acc.x += n0 * v0.x; acc.y += n0 * v0.y;
            acc.z += n0 * v0.z; acc.w += n0 * v0.w;
        }
    }
    // bias2 + relu
    float4 bb = ((const float4*)b2)[lane];
    acc.x = fmaxf(acc.x + bb.x, 0.f);
    acc.y = fmaxf(acc.y + bb.y, 0.f);
    acc.z = fmaxf(acc.z + bb.z, 0.f);
    acc.w = fmaxf(acc.w + bb.w, 0.f);
    // W3 projection (128 -> 2)
    int k = lane * 4;
    float a0 = acc.x * W3[2 * k + 0] + acc.y * W3[2 * k + 2] + acc.z * W3[2 * k + 4] + acc.w * W3[2 * k + 6];
    float a1 = acc.x * W3[2 * k + 1] + acc.y * W3[2 * k + 3] + acc.z * W3[2 * k + 5] + acc.w * W3[2 * k + 7];
#pragma unroll
    for (int o = 16; o; o >>= 1) {
        a0 += __shfl_xor_sync(0xffffffffu, a0, o);
        a1 += __shfl_xor_sync(0xffffffffu, a1, o);
    }
    if (lane == 0) {
        g_t3[d * 2 + 0] = a0;
        g_t3[d * 2 + 1] = a1;
    }
}

// ---------------- layer-3 pull + log_softmax fused ----------------
__global__ void k_pull2_lsm(const float* __restrict__ b3, float* __restrict__ out, int N) {
    int d = blockIdx.x * blockDim.x + threadIdx.x;
    if (d >= N) return;
    float dd = g_deg[d];
    float a0 = dd * dd * g_t3[2 * d + 0];
    float a1 = dd * dd * g_t3[2 * d + 1];
    int beg = g_off[d], end = g_off[d + 1];
    for (int i = beg; i < end; i++) {
        int s = g_csr[i];
        float nm = g_deg[s] * dd;
        a0 += nm * g_t3[2 * s + 0];
        a1 += nm * g_t3[2 * s + 1];
    }
    a0 += b3[0];
    a1 += b3[1];
    float m = fmaxf(a0, a1);
    float l = m + logf(expf(a0 - m) + expf(a1 - m));
    out[2 * d + 0] = a0 - l;
    out[2 * d + 1] = a1 - l;
}

// ---------------- orchestration ----------------
extern "C" void kernel_launch(void* const* d_in, const int* in_sizes, int n_in,
                              void* d_out, int out_size)
{
    const float* x  = (const float*)d_in[0];
    const float* W1 = (const float*)d_in[1];
    const float* b1 = (const float*)d_in[2];
    const float* W2 = (const float*)d_in[3];
    const float* b2 = (const float*)d_in[4];
    const float* W3 = (const float*)d_in[5];
    const float* b3 = (const float*)d_in[6];
    const void*  ei = (const void*)d_in[7];
    float* out = (float*)d_out;

    const int IN = 128;
    const int H1 = in_sizes[2];            // 256
    const int N  = in_sizes[0] / IN;       // 50000
    const int E  = in_sizes[7] / 2;        // 600000
    (void)n_in; (void)out_size;

    float *p_agg, *p_h1, *p_t;
    cudaGetSymbolAddress((void**)&p_agg, g_agg);
    cudaGetSymbolAddress((void**)&p_h1,  g_h1);
    cudaGetSymbolAddress((void**)&p_t,   g_t);

    const int T = 256;
    const int nodeBlocks  = (N + T - 1) / T;     // 196
    const int edgeBlocks  = (E + T - 1) / T;
    const int warpBlocksN = (N + 7) / 8;
    const int mTiles      = (N + 127) / 128;

    // graph prep
    k_init<<<nodeBlocks, T>>>((const unsigned*)ei, N);
    k_count<<<edgeBlocks, T>>>(ei, E, N);
    k_scan1<<<nodeBlocks, T>>>(N);
    k_scan23<<<nodeBlocks, T>>>(nodeBlocks, N);
    k_fill<<<edgeBlocks, T>>>(ei, E, N);

    // ---- layer 1: aggregate-first:  h1 = relu( (A x) W1 + b1 ) ----
    k_pull128<<<warpBlocksN, T>>>(x, p_agg, N);
    {
        dim3 grid(H1 / 128, mTiles);
        k_sgemm_pf<0><<<grid, 256>>>(N, H1, IN, p_agg, W1, b1, p_h1);
    }

    // ---- layer 2: transform-first:  t = h1 W2 ----
    {
        dim3 grid(1, mTiles);
        k_sgemm_pf<1><<<grid, 256>>>(N, 128, H1, p_h1, W2, nullptr, p_t);
    }

    // ---- layer 3 fused: t3 = relu(A t + b2) W3 ; out = lsm(A t3 + b3) ----
    k_pull_gemm3<<<warpBlocksN, T>>>(p_t, b2, W3, N);
    k_pull2_lsm<<<nodeBlocks, T>>>(b3, out, N);
}

// round 12
// speedup vs baseline: 1.4883x; 1.4883x over previous
#include <cuda_runtime.h>
#include <cstdint>

#define MAXN 50000
#define MAXE 600000

// ---------------- scratch ----------------
__device__ __align__(16) float g_deg[MAXN];        // dinv = rsqrt(1 + indeg)
__device__ int   g_cnt[MAXN];
__device__ int   g_off[MAXN + 1];
__device__ int   g_pos[MAXN];
__device__ int   g_csr[MAXE];
__device__ int   g_bsum[256];
__device__ __align__(16) float g_agg[MAXN * 128];
__device__ __align__(16) float g_h1 [MAXN * 256];
__device__ __align__(16) float g_t  [MAXN * 128];
__device__ __align__(16) float g_t3 [MAXN * 2];
__device__ int g_is32 = 0;   // probe only ever sets 1 (idempotent across graph replays)

// ---------------- graph prep ----------------
__global__ void k_init(const unsigned* __restrict__ w, int n) {
    int i = blockIdx.x * blockDim.x + threadIdx.x;
    if (i < n) g_cnt[i] = 0;
    if (i < 2048 && w[2 * i + 1] != 0u) g_is32 = 1;
}

__device__ __forceinline__ void decode_edge(const void* ei, int e, int E, int N, int& s, int& d) {
    if (g_is32) {
        const int* p = (const int*)ei;
        s = p[e]; d = p[E + e];
    } else {
        const long long* p = (const long long*)ei;
        s = (int)p[e]; d = (int)p[E + e];
    }
    s = min(max(s, 0), N - 1);
    d = min(max(d, 0), N - 1);
}

__global__ void k_count(const void* __restrict__ ei, int E, int N) {
    int e = blockIdx.x * blockDim.x + threadIdx.x;
    if (e >= E) return;
    int s, d;
    decode_edge(ei, e, E, N, s, d);
    atomicAdd(&g_cnt[d], 1);
}

__global__ __launch_bounds__(256) void k_scan1(int N) {
    __shared__ int sh[256];
    int i = blockIdx.x * 256 + threadIdx.x;
    int t = threadIdx.x;
    int v = (i < N) ? g_cnt[i] : 0;
    sh[t] = v;
    __syncthreads();
#pragma unroll
    for (int off = 1; off < 256; off <<= 1) {
        int u = (t >= off) ? sh[t - off] : 0;
        __syncthreads();
        sh[t] += u;
        __syncthreads();
    }
    if (i < N) g_off[i] = sh[t] - v;
    if (t == 255) g_bsum[blockIdx.x] = sh[255];
}

__global__ __launch_bounds__(256) void k_scan23(int nBlocks, int N) {
    __shared__ int sh[256];
    int t = threadIdx.x;
    int v = (t < nBlocks) ? g_bsum[t] : 0;
    sh[t] = v;
    __syncthreads();
#pragma unroll
    for (int off = 1; off < 256; off <<= 1) {
        int u = (t >= off) ? sh[t - off] : 0;
        __syncthreads();
        sh[t] += u;
        __syncthreads();
    }
    int pre = (blockIdx.x > 0) ? sh[blockIdx.x - 1] : 0;
    int i = blockIdx.x * 256 + t;
    if (i < N) {
        int o = g_off[i] + pre;
        g_off[i] = o;
        g_pos[i] = o;
        g_deg[i] = rsqrtf((float)(1 + g_cnt[i]));
    }
    if (blockIdx.x == 0 && t == 0) g_off[N] = sh[nBlocks - 1];
}

__global__ void k_fill(const void* __restrict__ ei, int E, int N) {
    int e = blockIdx.x * blockDim.x + threadIdx.x;
    if (e >= E) return;
    int s, d;
    decode_edge(ei, e, E, N, s, d);
    int p = atomicAdd(&g_pos[d], 1);
    g_csr[p] = s;
}

// ---------------- pull aggregation (C = 128) ----------------
__global__ __launch_bounds__(256) void k_pull128(const float* __restrict__ h,
                                                 float* __restrict__ out, int N) {
    int d = blockIdx.x * (blockDim.x >> 5) + (threadIdx.x >> 5);
    if (d >= N) return;
    int lane = threadIdx.x & 31;
    float dd = g_deg[d];
    float4 acc = ((const float4*)(h + (size_t)d * 128))[lane];
    float nms = dd * dd;
    acc.x *= nms; acc.y *= nms; acc.z *= nms; acc.w *= nms;
    const int beg = g_off[d], end = g_off[d + 1];
    for (int base = beg; base < end; base += 32) {
        int cnt = min(end - base, 32);
        int e = base + lane;
        int sE = (lane < cnt) ? g_csr[e] : 0;
        float nmE = (lane < cnt) ? g_deg[sE] * dd : 0.f;
        int j = 0;
        for (; j + 2 <= cnt; j += 2) {
            int   s0 = __shfl_sync(0xffffffffu, sE,  j);
            int   s1 = __shfl_sync(0xffffffffu, sE,  j + 1);
            float n0 = __shfl_sync(0xffffffffu, nmE, j);
            float n1 = __shfl_sync(0xffffffffu, nmE, j + 1);
            float4 v0 = ((const float4*)(h + (size_t)s0 * 128))[lane];
            float4 v1 = ((const float4*)(h + (size_t)s1 * 128))[lane];
            acc.x += n0 * v0.x + n1 * v1.x;
            acc.y += n0 * v0.y + n1 * v1.y;
            acc.z += n0 * v0.z + n1 * v1.z;
            acc.w += n0 * v0.w + n1 * v1.w;
        }
        if (j < cnt) {
            int   s0 = __shfl_sync(0xffffffffu, sE,  j);
            float n0 = __shfl_sync(0xffffffffu, nmE, j);
            float4 v0 = ((const float4*)(h + (size_t)s0 * 128))[lane];
            acc.x += n0 * v0.x; acc.y += n0 * v0.y;
            acc.z += n0 * v0.z; acc.w += n0 * v0.w;
        }
    }
    ((float4*)(out + (size_t)d * 128))[lane] = acc;
}

// ---------------- SGEMM, packed fma.rn.f32x2, BK=8, register prefetch ----------------
// MODE 0: C = relu(out + bias), MODE 1: C = out
template<int MODE>
__global__ __launch_bounds__(256) void k_sgemm_pf(
    int M, int Ntot, int K,
    const float* __restrict__ A, const float* __restrict__ B,
    const float* __restrict__ bias, float* __restrict__ C)
{
    __shared__ float As[8][128];
    __shared__ float Bs[8][128];
    const int tid = threadIdx.x;
    const int br = blockIdx.y, bc = blockIdx.x;
    const int rowA = tid >> 1;
    const int colA = (tid & 1) << 2;
    const int rowB = tid >> 5;
    const int colB = (tid & 31) << 2;
    const int tr = (tid >> 4) << 3;
    const int tc = (tid & 15) << 3;

    unsigned long long acc[8][4];
#pragma unroll
    for (int i = 0; i < 8; i++)
#pragma unroll
        for (int j = 0; j < 4; j++) acc[i][j] = 0ull;

    const int aRow = br * 128 + rowA;
    const bool aValid = aRow < M;
    const float* Ag = A + (size_t)aRow * K + colA;
    const float* Bg = B + (size_t)rowB * Ntot + bc * 128 + colB;

    float4 av = aValid ? *(const float4*)(Ag) : make_float4(0.f, 0.f, 0.f, 0.f);
    float4 bv = *(const float4*)(Bg);
    As[colA + 0][rowA] = av.x;
    As[colA + 1][rowA] = av.y;
    As[colA + 2][rowA] = av.z;
    As[colA + 3][rowA] = av.w;
    *(float4*)&Bs[rowB][colB] = bv;
    __syncthreads();

    for (int k0 = 0; k0 < K; k0 += 8) {
        const bool more = (k0 + 8) < K;
        if (more) {
            av = aValid ? *(const float4*)(Ag + k0 + 8) : make_float4(0.f, 0.f, 0.f, 0.f);
            bv = *(const float4*)(Bg + (size_t)(k0 + 8) * Ntot);
        }
#pragma unroll
        for (int k = 0; k < 8; ++k) {
            float4 ra0 = *(const float4*)&As[k][tr];
            float4 ra1 = *(const float4*)&As[k][tr + 4];
            unsigned long long b2[4];
#pragma unroll
            for (int j = 0; j < 4; j++)
                b2[j] = *(const unsigned long long*)&Bs[k][tc + j * 2];
            float ras[8] = {ra0.x, ra0.y, ra0.z, ra0.w, ra1.x, ra1.y, ra1.z, ra1.w};
#pragma unroll
            for (int i = 0; i < 8; i++) {
                unsigned long long a2;
                asm("mov.b64 %0, {%1, %1};" : "=l"(a2) : "f"(ras[i]));
#pragma unroll
                for (int j = 0; j < 4; j++)
                    asm("fma.rn.f32x2 %0, %1, %2, %3;"
                        : "=l"(acc[i][j]) : "l"(a2), "l"(b2[j]), "l"(acc[i][j]));
            }
        }
        __syncthreads();
        if (more) {
            As[colA + 0][rowA] = av.x;
            As[colA + 1][rowA] = av.y;
            As[colA + 2][rowA] = av.z;
            As[colA + 3][rowA] = av.w;
            *(float4*)&Bs[rowB][colB] = bv;
            __syncthreads();
        }
    }

#pragma unroll
    for (int i = 0; i < 8; i++) {
        int r = br * 128 + tr + i;
        if (r >= M) break;
#pragma unroll
        for (int jj = 0; jj < 2; jj++) {
            int c = bc * 128 + tc + jj * 4;
            float4 v;
            asm("mov.b64 {%0, %1}, %2;" : "=f"(v.x), "=f"(v.y) : "l"(acc[i][jj * 2 + 0]));
            asm("mov.b64 {%0, %1}, %2;" : "=f"(v.z), "=f"(v.w) : "l"(acc[i][jj * 2 + 1]));
            if (MODE == 0) {
                const float4 bb = *(const float4*)(bias + c);
                v.x = fmaxf(v.x + bb.x, 0.f);
                v.y = fmaxf(v.y + bb.y, 0.f);
                v.z = fmaxf(v.z + bb.z, 0.f);
                v.w = fmaxf(v.w + bb.w, 0.f);
            }
            *(float4*)&C[(size_t)r * Ntot + c] = v;
        }
    }
}

// ---------------- layer-3: fused bias2+relu, 128 -> 2 ----------------
__global__ void k_gemm3(const float* __restrict__ agg, const float* __restrict__ b2,
                        const float* __restrict__ W3, int M) {
    int node = blockIdx.x * (blockDim.x >> 5) + (threadIdx.x >> 5);
    if (node >= M) return;
    int lane = threadIdx.x & 31;
    float4 v  = ((const float4*)(agg + (size_t)node * 128))[lane];
    float4 bb = ((const float4*)b2)[lane];
    v.x = fmaxf(v.x + bb.x, 0.f);
    v.y = fmaxf(v.y + bb.y, 0.f);
    v.z = fmaxf(v.z + bb.z, 0.f);
    v.w = fmaxf(v.w + bb.w, 0.f);
    int k = lane * 4;
    float a0 = v.x * W3[2 * k + 0] + v.y * W3[2 * k + 2] + v.z * W3[2 * k + 4] + v.w * W3[2 * k + 6];
    float a1 = v.x * W3[2 * k + 1] + v.y * W3[2 * k + 3] + v.z * W3[2 * k + 5] + v.w * W3[2 * k + 7];
#pragma unroll
    for (int o = 16; o; o >>= 1) {
        a0 += __shfl_xor_sync(0xffffffffu, a0, o);
        a1 += __shfl_xor_sync(0xffffffffu, a1, o);
    }
    if (lane == 0) {
        g_t3[node * 2 + 0] = a0;
        g_t3[node * 2 + 1] = a1;
    }
}

// ---------------- layer-3 pull + log_softmax fused ----------------
__global__ void k_pull2_lsm(const float* __restrict__ b3, float* __restrict__ out, int N) {
    int d = blockIdx.x * blockDim.x + threadIdx.x;
    if (d >= N) return;
    float dd = g_deg[d];
    float2 self = ((const float2*)g_t3)[d];
    float a0 = dd * dd * self.x;
    float a1 = dd * dd * self.y;
    int beg = g_off[d], end = g_off[d + 1];
#pragma unroll 4
    for (int i = beg; i < end; i++) {
        int s = g_csr[i];
        float nm = g_deg[s] * dd;
        float2 v = ((const float2*)g_t3)[s];
        a0 += nm * v.x;
        a1 += nm * v.y;
    }
    a0 += b3[0];
    a1 += b3[1];
    float m = fmaxf(a0, a1);
    float l = m + logf(expf(a0 - m) + expf(a1 - m));
    out[2 * d + 0] = a0 - l;
    out[2 * d + 1] = a1 - l;
}

// ---------------- orchestration ----------------
extern "C" void kernel_launch(void* const* d_in, const int* in_sizes, int n_in,
                              void* d_out, int out_size)
{
    const float* x  = (const float*)d_in[0];
    const float* W1 = (const float*)d_in[1];
    const float* b1 = (const float*)d_in[2];
    const float* W2 = (const float*)d_in[3];
    const float* b2 = (const float*)d_in[4];
    const float* W3 = (const float*)d_in[5];
    const float* b3 = (const float*)d_in[6];
    const void*  ei = (const void*)d_in[7];
    float* out = (float*)d_out;

    const int IN = 128;
    const int H1 = in_sizes[2];            // 256
    const int N  = in_sizes[0] / IN;       // 50000
    const int E  = in_sizes[7] / 2;        // 600000
    (void)n_in; (void)out_size;

    float *p_agg, *p_h1, *p_t;
    cudaGetSymbolAddress((void**)&p_agg, g_agg);
    cudaGetSymbolAddress((void**)&p_h1,  g_h1);
    cudaGetSymbolAddress((void**)&p_t,   g_t);

    const int T = 256;
    const int nodeBlocks  = (N + T - 1) / T;     // 196
    const int edgeBlocks  = (E + T - 1) / T;
    const int warpBlocksN = (N + 7) / 8;
    const int mTiles      = (N + 127) / 128;

    // graph prep
    k_init<<<nodeBlocks, T>>>((const unsigned*)ei, N);
    k_count<<<edgeBlocks, T>>>(ei, E, N);
    k_scan1<<<nodeBlocks, T>>>(N);
    k_scan23<<<nodeBlocks, T>>>(nodeBlocks, N);
    k_fill<<<edgeBlocks, T>>>(ei, E, N);

    // ---- layer 1: aggregate-first:  h1 = relu( (A x) W1 + b1 ) ----
    k_pull128<<<warpBlocksN, T>>>(x, p_agg, N);
    {
        dim3 grid(H1 / 128, mTiles);
        k_sgemm_pf<0><<<grid, 256>>>(N, H1, IN, p_agg, W1, b1, p_h1);
    }

    // ---- layer 2: transform-first:  t = h1 W2 ----
    {
        dim3 grid(1, mTiles);
        k_sgemm_pf<1><<<grid, 256>>>(N, 128, H1, p_h1, W2, nullptr, p_t);
    }
    k_pull128<<<warpBlocksN, T>>>(p_t, p_agg, N);

    // ---- layer 3: h2 = relu(agg+b2) fused; t3 = h2 W3 ; out = lsm(A t3 + b3) ----
    k_gemm3<<<warpBlocksN, T>>>(p_agg, b2, W3, N);
    k_pull2_lsm<<<nodeBlocks, T>>>(b3, out, N);
}

// round 13
// speedup vs baseline: 1.5351x; 1.0314x over previous
#include <cuda_runtime.h>
#include <cstdint>

#define MAXN 50000
#define MAXE 600000

// ---------------- scratch ----------------
__device__ __align__(16) float g_deg[MAXN];        // dinv = rsqrt(1 + indeg)
__device__ int   g_cnt[MAXN];
__device__ int   g_off[MAXN + 1];
__device__ int   g_pos[MAXN];
__device__ int   g_csr[MAXE];
__device__ int   g_bsum[256];
__device__ __align__(16) float g_agg[MAXN * 128];
__device__ __align__(16) float g_h1 [MAXN * 256];
__device__ __align__(16) float g_t  [MAXN * 128];
__device__ __align__(16) float g_t3 [MAXN * 2];
__device__ int g_is32 = 0;   // probe only ever sets 1 (idempotent across graph replays)

// ---------------- graph prep ----------------
__global__ void k_init(const unsigned* __restrict__ w, int n) {
    int i = blockIdx.x * blockDim.x + threadIdx.x;
    if (i < n) g_cnt[i] = 0;
    if (i < 2048 && w[2 * i + 1] != 0u) g_is32 = 1;
}

__device__ __forceinline__ void decode_edge(const void* ei, int e, int E, int N, int& s, int& d) {
    if (g_is32) {
        const int* p = (const int*)ei;
        s = p[e]; d = p[E + e];
    } else {
        const long long* p = (const long long*)ei;
        s = (int)p[e]; d = (int)p[E + e];
    }
    s = min(max(s, 0), N - 1);
    d = min(max(d, 0), N - 1);
}

__global__ void k_count(const void* __restrict__ ei, int E, int N) {
    int e = blockIdx.x * blockDim.x + threadIdx.x;
    if (e >= E) return;
    int s, d;
    decode_edge(ei, e, E, N, s, d);
    atomicAdd(&g_cnt[d], 1);
}

__global__ __launch_bounds__(256) void k_scan1(int N) {
    __shared__ int sh[256];
    int i = blockIdx.x * 256 + threadIdx.x;
    int t = threadIdx.x;
    int v = (i < N) ? g_cnt[i] : 0;
    sh[t] = v;
    __syncthreads();
#pragma unroll
    for (int off = 1; off < 256; off <<= 1) {
        int u = (t >= off) ? sh[t - off] : 0;
        __syncthreads();
        sh[t] += u;
        __syncthreads();
    }
    if (i < N) g_off[i] = sh[t] - v;
    if (t == 255) g_bsum[blockIdx.x] = sh[255];
}

__global__ __launch_bounds__(256) void k_scan23(int nBlocks, int N) {
    __shared__ int sh[256];
    int t = threadIdx.x;
    int v = (t < nBlocks) ? g_bsum[t] : 0;
    sh[t] = v;
    __syncthreads();
#pragma unroll
    for (int off = 1; off < 256; off <<= 1) {
        int u = (t >= off) ? sh[t - off] : 0;
        __syncthreads();
        sh[t] += u;
        __syncthreads();
    }
    int pre = (blockIdx.x > 0) ? sh[blockIdx.x - 1] : 0;
    int i = blockIdx.x * 256 + t;
    if (i < N) {
        int o = g_off[i] + pre;
        g_off[i] = o;
        g_pos[i] = o;
        g_deg[i] = rsqrtf((float)(1 + g_cnt[i]));
    }
    if (blockIdx.x == 0 && t == 0) g_off[N] = sh[nBlocks - 1];
}

__global__ void k_fill(const void* __restrict__ ei, int E, int N) {
    int e = blockIdx.x * blockDim.x + threadIdx.x;
    if (e >= E) return;
    int s, d;
    decode_edge(ei, e, E, N, s, d);
    int p = atomicAdd(&g_pos[d], 1);
    g_csr[p] = s;
}

// ---------------- pull aggregation (C = 128) ----------------
__global__ __launch_bounds__(256) void k_pull128(const float* __restrict__ h,
                                                 float* __restrict__ out, int N) {
    int d = blockIdx.x * (blockDim.x >> 5) + (threadIdx.x >> 5);
    if (d >= N) return;
    int lane = threadIdx.x & 31;
    float dd = g_deg[d];
    float4 acc = ((const float4*)(h + (size_t)d * 128))[lane];
    float nms = dd * dd;
    acc.x *= nms; acc.y *= nms; acc.z *= nms; acc.w *= nms;
    const int beg = g_off[d], end = g_off[d + 1];
    for (int base = beg; base < end; base += 32) {
        int cnt = min(end - base, 32);
        int e = base + lane;
        int sE = (lane < cnt) ? g_csr[e] : 0;
        float nmE = (lane < cnt) ? g_deg[sE] * dd : 0.f;
        int j = 0;
        for (; j + 2 <= cnt; j += 2) {
            int   s0 = __shfl_sync(0xffffffffu, sE,  j);
            int   s1 = __shfl_sync(0xffffffffu, sE,  j + 1);
            float n0 = __shfl_sync(0xffffffffu, nmE, j);
            float n1 = __shfl_sync(0xffffffffu, nmE, j + 1);
            float4 v0 = ((const float4*)(h + (size_t)s0 * 128))[lane];
            float4 v1 = ((const float4*)(h + (size_t)s1 * 128))[lane];
            acc.x += n0 * v0.x + n1 * v1.x;
            acc.y += n0 * v0.y + n1 * v1.y;
            acc.z += n0 * v0.z + n1 * v1.z;
            acc.w += n0 * v0.w + n1 * v1.w;
        }
        if (j < cnt) {
            int   s0 = __shfl_sync(0xffffffffu, sE,  j);
            float n0 = __shfl_sync(0xffffffffu, nmE, j);
            float4 v0 = ((const float4*)(h + (size_t)s0 * 128))[lane];
            acc.x += n0 * v0.x; acc.y += n0 * v0.y;
            acc.z += n0 * v0.z; acc.w += n0 * v0.w;
        }
    }
    ((float4*)(out + (size_t)d * 128))[lane] = acc;
}

// ---------------- SGEMM, packed fma.rn.f32x2, BK=8, register prefetch ----------------
// MODE 0: C = relu(out + bias), MODE 1: C = out
template<int MODE>
__global__ __launch_bounds__(256) void k_sgemm_pf(
    int M, int Ntot, int K,
    const float* __restrict__ A, const float* __restrict__ B,
    const float* __restrict__ bias, float* __restrict__ C)
{
    __shared__ float As[8][128];
    __shared__ float Bs[8][128];
    const int tid = threadIdx.x;
    const int br = blockIdx.y, bc = blockIdx.x;
    const int rowA = tid >> 1;
    const int colA = (tid & 1) << 2;
    const int rowB = tid >> 5;
    const int colB = (tid & 31) << 2;
    const int tr = (tid >> 4) << 3;
    const int tc = (tid & 15) << 3;

    unsigned long long acc[8][4];
#pragma unroll
    for (int i = 0; i < 8; i++)
#pragma unroll
        for (int j = 0; j < 4; j++) acc[i][j] = 0ull;

    const int aRow = br * 128 + rowA;
    const bool aValid = aRow < M;
    const float* Ag = A + (size_t)aRow * K + colA;
    const float* Bg = B + (size_t)rowB * Ntot + bc * 128 + colB;

    float4 av = aValid ? *(const float4*)(Ag) : make_float4(0.f, 0.f, 0.f, 0.f);
    float4 bv = *(const float4*)(Bg);
    As[colA + 0][rowA] = av.x;
    As[colA + 1][rowA] = av.y;
    As[colA + 2][rowA] = av.z;
    As[colA + 3][rowA] = av.w;
    *(float4*)&Bs[rowB][colB] = bv;
    __syncthreads();

    for (int k0 = 0; k0 < K; k0 += 8) {
        const bool more = (k0 + 8) < K;
        if (more) {
            av = aValid ? *(const float4*)(Ag + k0 + 8) : make_float4(0.f, 0.f, 0.f, 0.f);
            bv = *(const float4*)(Bg + (size_t)(k0 + 8) * Ntot);
        }
#pragma unroll
        for (int k = 0; k < 8; ++k) {
            float4 ra0 = *(const float4*)&As[k][tr];
            float4 ra1 = *(const float4*)&As[k][tr + 4];
            unsigned long long b2[4];
#pragma unroll
            for (int j = 0; j < 4; j++)
                b2[j] = *(const unsigned long long*)&Bs[k][tc + j * 2];
            float ras[8] = {ra0.x, ra0.y, ra0.z, ra0.w, ra1.x, ra1.y, ra1.z, ra1.w};
#pragma unroll
            for (int i = 0; i < 8; i++) {
                unsigned long long a2;
                asm("mov.b64 %0, {%1, %1};" : "=l"(a2) : "f"(ras[i]));
#pragma unroll
                for (int j = 0; j < 4; j++)
                    asm("fma.rn.f32x2 %0, %1, %2, %3;"
                        : "=l"(acc[i][j]) : "l"(a2), "l"(b2[j]), "l"(acc[i][j]));
            }
        }
        __syncthreads();
        if (more) {
            As[colA + 0][rowA] = av.x;
            As[colA + 1][rowA] = av.y;
            As[colA + 2][rowA] = av.z;
            As[colA + 3][rowA] = av.w;
            *(float4*)&Bs[rowB][colB] = bv;
            __syncthreads();
        }
    }

#pragma unroll
    for (int i = 0; i < 8; i++) {
        int r = br * 128 + tr + i;
        if (r >= M) break;
#pragma unroll
        for (int jj = 0; jj < 2; jj++) {
            int c = bc * 128 + tc + jj * 4;
            float4 v;
            asm("mov.b64 {%0, %1}, %2;" : "=f"(v.x), "=f"(v.y) : "l"(acc[i][jj * 2 + 0]));
            asm("mov.b64 {%0, %1}, %2;" : "=f"(v.z), "=f"(v.w) : "l"(acc[i][jj * 2 + 1]));
            if (MODE == 0) {
                const float4 bb = *(const float4*)(bias + c);
                v.x = fmaxf(v.x + bb.x, 0.f);
                v.y = fmaxf(v.y + bb.y, 0.f);
                v.z = fmaxf(v.z + bb.z, 0.f);
                v.w = fmaxf(v.w + bb.w, 0.f);
            }
            *(float4*)&C[(size_t)r * Ntot + c] = v;
        }
    }
}

// ---------------- fused pull(t) + bias2 + relu + W3 projection -> t3 ----------------
__global__ __launch_bounds__(256) void k_pull_gemm3(const float* __restrict__ t,
                                                    const float* __restrict__ b2,
                                                    const float* __restrict__ W3, int N) {
    int d = blockIdx.x * (blockDim.x >> 5) + (threadIdx.x >> 5);
    if (d >= N) return;
    int lane = threadIdx.x & 31;
    float dd = g_deg[d];
    float4 acc = ((const float4*)(t + (size_t)d * 128))[lane];
    float nms = dd * dd;
    acc.x *= nms; acc.y *= nms; acc.z *= nms; acc.w *= nms;
    const int beg = g_off[d], end = g_off[d + 1];
    for (int base = beg; base < end; base += 32) {
        int cnt = min(end - base, 32);
        int e = base + lane;
        int sE = (lane < cnt) ? g_csr[e] : 0;
        float nmE = (lane < cnt) ? g_deg[sE] * dd : 0.f;
        int j = 0;
        for (; j + 2 <= cnt; j += 2) {
            int   s0 = __shfl_sync(0xffffffffu, sE,  j);
            int   s1 = __shfl_sync(0xffffffffu, sE,  j + 1);
            float n0 = __shfl_sync(0xffffffffu, nmE, j);
            float n1 = __shfl_sync(0xffffffffu, nmE, j + 1);
            float4 v0 = ((const float4*)(t + (size_t)s0 * 128))[lane];
            float4 v1 = ((const float4*)(t + (size_t)s1 * 128))[lane];
            acc.x += n0 * v0.x + n1 * v1.x;
            acc.y += n0 * v0.y + n1 * v1.y;
            acc.z += n0 * v0.z + n1 * v1.z;
            acc.w += n0 * v0.w + n1 * v1.w;
        }
        if (j < cnt) {
            int   s0 = __shfl_sync(0xffffffffu, sE,  j);
            float n0 = __shfl_sync(0xffffffffu, nmE, j);
            float4 v0 = ((const float4*)(t + (size_t)s0 * 128))[lane];
            acc.x += n0 * v0.x; acc.y += n0 * v0.y;
            acc.z += n0 * v0.z; acc.w += n0 * v0.w;
        }
    }
    // bias2 + relu
    float4 bb = ((const float4*)b2)[lane];
    acc.x = fmaxf(acc.x + bb.x, 0.f);
    acc.y = fmaxf(acc.y + bb.y, 0.f);
    acc.z = fmaxf(acc.z + bb.z, 0.f);
    acc.w = fmaxf(acc.w + bb.w, 0.f);
    // W3 projection (128 -> 2)
    int k = lane * 4;
    float a0 = acc.x * W3[2 * k + 0] + acc.y * W3[2 * k + 2] + acc.z * W3[2 * k + 4] + acc.w * W3[2 * k + 6];
    float a1 = acc.x * W3[2 * k + 1] + acc.y * W3[2 * k + 3] + acc.z * W3[2 * k + 5] + acc.w * W3[2 * k + 7];
#pragma unroll
    for (int o = 16; o; o >>= 1) {
        a0 += __shfl_xor_sync(0xffffffffu, a0, o);
        a1 += __shfl_xor_sync(0xffffffffu, a1, o);
    }
    if (lane == 0) {
        g_t3[d * 2 + 0] = a0;
        g_t3[d * 2 + 1] = a1;
    }
}

// ---------------- layer-3 pull + log_softmax fused ----------------
__global__ void k_pull2_lsm(const float* __restrict__ b3, float* __restrict__ out, int N) {
    int d = blockIdx.x * blockDim.x + threadIdx.x;
    if (d >= N) return;
    float dd = g_deg[d];
    float2 self = ((const float2*)g_t3)[d];
    float a0 = dd * dd * self.x;
    float a1 = dd * dd * self.y;
    int beg = g_off[d], end = g_off[d + 1];
#pragma unroll 4
    for (int i = beg; i < end; i++) {
        int s = g_csr[i];
        float nm = g_deg[s] * dd;
        float2 v = ((const float2*)g_t3)[s];
        a0 += nm * v.x;
        a1 += nm * v.y;
    }
    a0 += b3[0];
    a1 += b3[1];
    float m = fmaxf(a0, a1);
    float l = m + __logf(__expf(a0 - m) + __expf(a1 - m));
    out[2 * d + 0] = a0 - l;
    out[2 * d + 1] = a1 - l;
}

// ---------------- orchestration ----------------
extern "C" void kernel_launch(void* const* d_in, const int* in_sizes, int n_in,
                              void* d_out, int out_size)
{
    const float* x  = (const float*)d_in[0];
    const float* W1 = (const float*)d_in[1];
    const float* b1 = (const float*)d_in[2];
    const float* W2 = (const float*)d_in[3];
    const float* b2 = (const float*)d_in[4];
    const float* W3 = (const float*)d_in[5];
    const float* b3 = (const float*)d_in[6];
    const void*  ei = (const void*)d_in[7];
    float* out = (float*)d_out;

    const int IN = 128;
    const int H1 = in_sizes[2];            // 256
    const int N  = in_sizes[0] / IN;       // 50000
    const int E  = in_sizes[7] / 2;        // 600000
    (void)n_in; (void)out_size;

    float *p_agg, *p_h1, *p_t;
    cudaGetSymbolAddress((void**)&p_agg, g_agg);
    cudaGetSymbolAddress((void**)&p_h1,  g_h1);
    cudaGetSymbolAddress((void**)&p_t,   g_t);

    const int T = 256;
    const int nodeBlocks  = (N + T - 1) / T;     // 196
    const int edgeBlocks  = (E + T - 1) / T;
    const int warpBlocksN = (N + 7) / 8;
    const int mTiles      = (N + 127) / 128;

    // graph prep
    k_init<<<nodeBlocks, T>>>((const unsigned*)ei, N);
    k_count<<<edgeBlocks, T>>>(ei, E, N);
    k_scan1<<<nodeBlocks, T>>>(N);
    k_scan23<<<nodeBlocks, T>>>(nodeBlocks, N);
    k_fill<<<edgeBlocks, T>>>(ei, E, N);

    // ---- layer 1: aggregate-first:  h1 = relu( (A x) W1 + b1 ) ----
    k_pull128<<<warpBlocksN, T>>>(x, p_agg, N);
    {
        dim3 grid(H1 / 128, mTiles);
        k_sgemm_pf<0><<<grid, 256>>>(N, H1, IN, p_agg, W1, b1, p_h1);
    }

    // ---- layer 2: transform-first:  t = h1 W2 ----
    {
        dim3 grid(1, mTiles);
        k_sgemm_pf<1><<<grid, 256>>>(N, 128, H1, p_h1, W2, nullptr, p_t);
    }

    // ---- layer 3 fused: t3 = relu(A t + b2) W3 ; out = lsm(A t3 + b3) ----
    k_pull_gemm3<<<warpBlocksN, T>>>(p_t, b2, W3, N);
    k_pull2_lsm<<<nodeBlocks, T>>>(b3, out, N);
}